// round 7
// baseline (speedup 1.0000x reference)
#include <cuda_runtime.h>
#include <cstdint>

// Problem constants
#define B_   4
#define TE   512
#define TD   256
#define DE   512
#define DD   512
#define U_   128
#define NROW_E (B_*TE)   // 2048 encoder rows
#define NROW_D (B_*TD)   // 1024 decoder rows
#define TT   4           // decoder-t tile per block (grid=256 -> 2 blocks/SM, 100% occ)
#define CTX_OFF (NROW_D*DE)   // context elements before attn weights in d_out

// Scratch (static device globals: no allocation allowed)
__device__ float g_encT[U_ * NROW_E];   // enc projection, TRANSPOSED: [u][row]
__device__ float g_dec [NROW_D * U_];   // dec projection: [row][u]

__device__ __forceinline__ float tanh_fast(float x) {
    float y;
    asm("tanh.approx.f32 %0, %1;" : "=f"(y) : "f"(x));
    return y;
}

#define FMA_F32X2(d, a, b) \
    asm("fma.rn.f32x2 %0, %1, %2, %0;" : "+l"(d) : "l"(a), "l"(b))

// ---------------------------------------------------------------------------
// Kernel 1: both input projections.
//   enc_p[row,u] = enc[row,:] @ W1[:,u] + b1[u]   (stored transposed [u][row])
//   dec_p[row,u] = dec[row,:] @ W2[:,u] + b2[u]   (stored [row][u])
// ---------------------------------------------------------------------------
__global__ __launch_bounds__(256) void proj_kernel(
    const float* __restrict__ enc, const float* __restrict__ dec,
    const float* __restrict__ W1, const float* __restrict__ b1,
    const float* __restrict__ W2, const float* __restrict__ b2)
{
    __shared__ float sX[16][512];

    const int ENC_BLOCKS = NROW_E / 16;   // 128
    bool isDec = (blockIdx.x >= ENC_BLOCKS);
    int blk = isDec ? (blockIdx.x - ENC_BLOCKS) : blockIdx.x;
    int rowBase = blk * 16;

    const float* X    = isDec ? dec : enc;
    const float* W    = isDec ? W2  : W1;
    const float* bias = isDec ? b2  : b1;

    const float4* Xv  = (const float4*)(X + (size_t)rowBase * 512);
    float4*       sXv = (float4*)&sX[0][0];
    for (int j = threadIdx.x; j < 16 * 128; j += 256) sXv[j] = Xv[j];
    __syncthreads();

    int u  = threadIdx.x & 127;
    int rg = threadIdx.x >> 7;

    float acc[8];
    float bv = bias[u];
#pragma unroll
    for (int i = 0; i < 8; i++) acc[i] = bv;

    const float* Wp = W + u;
#pragma unroll 4
    for (int k = 0; k < 512; k++) {
        float wv = Wp[(size_t)k * U_];
#pragma unroll
        for (int i = 0; i < 8; i++)
            acc[i] += sX[rg * 8 + i][k] * wv;
    }

    if (isDec) {
#pragma unroll
        for (int i = 0; i < 8; i++)
            g_dec[(size_t)(rowBase + rg * 8 + i) * U_ + u] = acc[i];
    } else {
#pragma unroll
        for (int i = 0; i < 8; i++)
            g_encT[(size_t)u * NROW_E + rowBase + rg * 8 + i] = acc[i];
    }
}

// ---------------------------------------------------------------------------
// Kernel 2: fused score + softmax + context for a (b, 4-t tile).
// Grid: B * (TD/TT) = 256 blocks, 1024 threads, 2 blocks/SM (100% occ).
//   Score:   thread = (e = tid&511, half = tid>>9); half owns 2 of the 4 t's.
//   Context: thread = (d = tid&511, half); half owns 256 of the 512 e's,
//            partials combined through s_w (reused after weights consumed).
// ---------------------------------------------------------------------------
__global__ __launch_bounds__(1024, 2) void attn_kernel(
    const float* __restrict__ enc,
    const float* __restrict__ Vw,
    float* __restrict__ out)
{
    __shared__ float sdp[TT][U_];            // dec_p tile
    __shared__ float sV[U_];
    __shared__ float sred[TT * 16];
    __shared__ float smax[TT];
    __shared__ float ssum[TT];
    __shared__ __align__(16) float s_w[TE][TT];   // weights [e][t] -> later ctx partials [d][t]

    int b  = blockIdx.x >> 6;                // / (TD/TT = 64)
    int t0 = (blockIdx.x & 63) * TT;
    int tid  = threadIdx.x;
    int half = tid >> 9;                     // 0 or 1
    int eth  = tid & 511;                    // e (score) / d (context)

    // load dec_p tile (4 rows x 128) + V
    if (tid < TT * U_)
        ((float*)sdp)[tid] = g_dec[(size_t)(b * TD + t0) * U_ + tid];
    if (tid < U_) sV[tid] = Vw[tid];
    __syncthreads();

    // ---- score phase: thread owns e = eth, t in [half*2, half*2+2) ----
    float acc0 = 0.f, acc1 = 0.f;

    const float* ep = g_encT + (size_t)b * TE + eth;
    const int tb = half * 2;
#pragma unroll 4
    for (int u = 0; u < U_; u++) {
        float ev = ep[(size_t)u * NROW_E];   // coalesced, L2-resident
        float vv = sV[u];
        acc0 += vv * tanh_fast(ev + sdp[tb + 0][u]);
        acc1 += vv * tanh_fast(ev + sdp[tb + 1][u]);
    }
    // (V_b dropped: softmax is shift-invariant; cancels in both outputs)

    // ---- softmax over e (512 threads per half), per t ----
    int lane = tid & 31, wid = tid >> 5;     // 32 warps
    int wloc = wid & 15;                     // warp index within half

    // max
    {
        float v0 = acc0, v1 = acc1;
#pragma unroll
        for (int o = 16; o; o >>= 1) {
            v0 = fmaxf(v0, __shfl_xor_sync(0xffffffffu, v0, o));
            v1 = fmaxf(v1, __shfl_xor_sync(0xffffffffu, v1, o));
        }
        if (lane == 0) {
            sred[(tb + 0) * 16 + wloc] = v0;
            sred[(tb + 1) * 16 + wloc] = v1;
        }
    }
    __syncthreads();
    if (wid < TT) {
        float v = (lane < 16) ? sred[wid * 16 + lane] : -3.0e38f;
#pragma unroll
        for (int o = 8; o; o >>= 1)
            v = fmaxf(v, __shfl_xor_sync(0xffffffffu, v, o));
        if (lane == 0) smax[wid] = v;
    }
    __syncthreads();

    // exp + sum
    float p0 = __expf(acc0 - smax[tb + 0]);
    float p1 = __expf(acc1 - smax[tb + 1]);
    {
        float v0 = p0, v1 = p1;
#pragma unroll
        for (int o = 16; o; o >>= 1) {
            v0 += __shfl_xor_sync(0xffffffffu, v0, o);
            v1 += __shfl_xor_sync(0xffffffffu, v1, o);
        }
        if (lane == 0) {
            sred[(tb + 0) * 16 + wloc] = v0;
            sred[(tb + 1) * 16 + wloc] = v1;
        }
    }
    __syncthreads();
    if (wid < TT) {
        float v = (lane < 16) ? sred[wid * 16 + lane] : 0.f;
#pragma unroll
        for (int o = 8; o; o >>= 1)
            v += __shfl_xor_sync(0xffffffffu, v, o);
        if (lane == 0) ssum[wid] = v;
    }
    __syncthreads();

    // weights -> smem [e][t] (for context) and gmem output
    {
        float w0 = p0 / ssum[tb + 0];
        float w1 = p1 / ssum[tb + 1];
        *(float2*)&s_w[eth][tb] = make_float2(w0, w1);
        out[CTX_OFF + (size_t)(b * TD + t0 + tb + 0) * TE + eth] = w0;
        out[CTX_OFF + (size_t)(b * TD + t0 + tb + 1) * TE + eth] = w1;
    }
    __syncthreads();

    // ---- context phase: thread owns d = eth, e-range [half*256, +256) ----
    // context[t,d] = sum_e w[t,e] * enc[b,e,d]; packed f32x2 FMA (2 t per op)
    const float* eb = enc + ((size_t)b * TE + half * 256) * DE + eth;

    unsigned long long cc0 = 0ULL, cc1 = 0ULL;

#pragma unroll 4
    for (int ei = 0; ei < 256; ei++) {
        float ev = __ldg(eb + (size_t)ei * DE);     // coalesced, L2-resident
        unsigned long long evv;
        asm("mov.b64 %0, {%1, %2};" : "=l"(evv) : "f"(ev), "f"(ev));
        ulonglong2 q = *(const ulonglong2*)&s_w[half * 256 + ei][0]; // (w0,w1),(w2,w3)
        FMA_F32X2(cc0, q.x, evv);
        FMA_F32X2(cc1, q.y, evv);
    }

    float c[TT];
    asm("mov.b64 {%0, %1}, %2;" : "=f"(c[0]), "=f"(c[1]) : "l"(cc0));
    asm("mov.b64 {%0, %1}, %2;" : "=f"(c[2]), "=f"(c[3]) : "l"(cc1));

    // combine the two e-half partials through s_w (weights no longer needed)
    __syncthreads();
    if (half == 1)
        *(float4*)&s_w[eth][0] = make_float4(c[0], c[1], c[2], c[3]);
    __syncthreads();
    if (half == 0) {
        float4 o0 = *(float4*)&s_w[eth][0];
        c[0] += o0.x; c[1] += o0.y; c[2] += o0.z; c[3] += o0.w;
#pragma unroll
        for (int t = 0; t < TT; t++)
            out[(size_t)(b * TD + t0 + t) * DE + eth] = c[t];
    }
}

// ---------------------------------------------------------------------------
extern "C" void kernel_launch(void* const* d_in, const int* in_sizes, int n_in,
                              void* d_out, int out_size)
{
    (void)in_sizes; (void)n_in; (void)out_size;
    const float* enc = (const float*)d_in[0];
    const float* dec = (const float*)d_in[1];
    const float* W1  = (const float*)d_in[2];
    const float* b1  = (const float*)d_in[3];
    const float* W2  = (const float*)d_in[4];
    const float* b2  = (const float*)d_in[5];
    const float* Vw  = (const float*)d_in[6];
    // d_in[7] = V_b: unused (cancels in softmax)
    float* out = (float*)d_out;

    proj_kernel<<<NROW_E / 16 + NROW_D / 16, 256>>>(enc, dec, W1, b1, W2, b2);
    attn_kernel<<<B_ * (TD / TT), 1024>>>(enc, Vw, out);
}